// round 12
// baseline (speedup 1.0000x reference)
#include <cuda_runtime.h>
#include <cuda_fp16.h>
#include <stdint.h>
#include <math.h>

#define BB 8
#define NA 2000
#define DD 256
#define EE 64000
#define KNUMH 1098       /* half-space k-vectors (m = 0..1097) */
#define KP 1152          /* 128 * 9, padded with G=0, cos/sin=0 */
#define PI_F 3.14159265358979f
#define C_SELF (-0.7978845608028654f)   /* -sqrt(2/pi)/sigma */

/* ---------------- scratch (device globals; no allocations allowed) -------- */
__device__ float g_q  [BB*NA*DD];
__device__ float g_pot[BB*NA*DD];
__device__ __align__(16) half g_qh  [BB*NA*DD];
__device__ __align__(16) half g_cosh[(size_t)BB*NA*KP];
__device__ __align__(16) half g_sinh[(size_t)BB*NA*KP];
__device__ __align__(16) half g_Sch [BB*KP*DD];
__device__ __align__(16) half g_Ssh [BB*KP*DD];
__device__ int   g_cnt[BB*NA];
__device__ int   g_off[BB*NA];
__device__ int   g_fil[BB*NA];
__device__ int   g_elj[BB*EE];
__device__ float g_elv[BB*EE];

/* ---------------- MMA / ldmatrix / cp.async helpers ------------------------ */
__device__ __forceinline__ unsigned sptr(const void* p) {
    return (unsigned)__cvta_generic_to_shared(p);
}
__device__ __forceinline__ void ldsm4(unsigned* r, unsigned a) {
    asm volatile("ldmatrix.sync.aligned.m8n8.x4.shared.b16 {%0,%1,%2,%3},[%4];"
        : "=r"(r[0]), "=r"(r[1]), "=r"(r[2]), "=r"(r[3]) : "r"(a));
}
__device__ __forceinline__ void ldsm4t(unsigned* r, unsigned a) {
    asm volatile("ldmatrix.sync.aligned.m8n8.x4.trans.shared.b16 {%0,%1,%2,%3},[%4];"
        : "=r"(r[0]), "=r"(r[1]), "=r"(r[2]), "=r"(r[3]) : "r"(a));
}
__device__ __forceinline__ void mma16816(float* d, const unsigned* a,
                                         unsigned b0, unsigned b1) {
    asm volatile(
        "mma.sync.aligned.m16n8k16.row.col.f32.f16.f16.f32 "
        "{%0,%1,%2,%3},{%4,%5,%6,%7},{%8,%9},{%0,%1,%2,%3};"
        : "+f"(d[0]), "+f"(d[1]), "+f"(d[2]), "+f"(d[3])
        : "r"(a[0]), "r"(a[1]), "r"(a[2]), "r"(a[3]), "r"(b0), "r"(b1));
}
__device__ __forceinline__ unsigned f2tf(float x) {
    unsigned r; asm("cvt.rna.tf32.f32 %0, %1;" : "=r"(r) : "f"(x)); return r;
}
__device__ __forceinline__ void mma_tf32(float* d, unsigned a0, unsigned a1,
                                         unsigned a2, unsigned a3,
                                         unsigned b0, unsigned b1) {
    asm volatile(
        "mma.sync.aligned.m16n8k8.row.col.f32.tf32.tf32.f32 "
        "{%0,%1,%2,%3},{%4,%5,%6,%7},{%8,%9},{%0,%1,%2,%3};"
        : "+f"(d[0]), "+f"(d[1]), "+f"(d[2]), "+f"(d[3])
        : "r"(a0), "r"(a1), "r"(a2), "r"(a3), "r"(b0), "r"(b1));
}
#define CPA16(d, s)     asm volatile("cp.async.ca.shared.global [%0], [%1], 16;" :: "r"(d), "l"(s))
#define CPA16Z(d, s, n) asm volatile("cp.async.ca.shared.global [%0], [%1], 16, %2;" :: "r"(d), "l"(s), "r"(n))
#define CPCOMMIT()      asm volatile("cp.async.commit_group;")
#define CPWAIT1()       asm volatile("cp.async.wait_group 1;")

/* ---------------- Green's function evaluation (inline) --------------------- */
__device__ __forceinline__ void cell_inv(const float* C, float* iM, float* absdet) {
    float c00=C[0],c01=C[1],c02=C[2];
    float c10=C[3],c11=C[4],c12=C[5];
    float c20=C[6],c21=C[7],c22=C[8];
    float det = c00*(c11*c22-c12*c21) - c01*(c10*c22-c12*c20) + c02*(c10*c21-c11*c20);
    float id = 1.0f/det;
    iM[0]=(c11*c22-c12*c21)*id; iM[1]=(c02*c21-c01*c22)*id; iM[2]=(c01*c12-c02*c11)*id;
    iM[3]=(c12*c20-c10*c22)*id; iM[4]=(c00*c22-c02*c20)*id; iM[5]=(c02*c10-c00*c12)*id;
    iM[6]=(c10*c21-c11*c20)*id; iM[7]=(c01*c20-c00*c21)*id; iM[8]=(c00*c11-c01*c10)*id;
    *absdet = fabsf(det);
}
__device__ __forceinline__ float green_eval(int k, const float* iM, float absdet) {
    if (k >= KNUMH) return 0.f;
    float ni = (float)(k/169 - 6);
    float nj = (float)((k/13)%13 - 6);
    float nk = (float)(k%13 - 6);
    float kx = 2.0f*PI_F*(iM[0]*ni + iM[1]*nj + iM[2]*nk);
    float ky = 2.0f*PI_F*(iM[3]*ni + iM[4]*nj + iM[5]*nk);
    float kz = 2.0f*PI_F*(iM[6]*ni + iM[7]*nj + iM[8]*nk);
    float k2 = kx*kx + ky*ky + kz*kz;
    return 8.0f*PI_F/absdet * __expf(-0.5f*k2) / k2;   /* x2 for ±k pair */
}

/* ------ charges = features @ W^T + b (tf32 MMA, K-outer, A read once) ------ */
/* grid 250, 256 threads, 8 warps = 4m x 2n. block tile 64m x 256n. */
__global__ void __launch_bounds__(256) k_charges(const float* __restrict__ A,
                                                 const float* __restrict__ Wm,
                                                 const float* __restrict__ bias) {
    __shared__ unsigned sA[64][20];
    __shared__ unsigned sB[16][264];
    int m0 = blockIdx.x * 64;
    int tid = threadIdx.x, warp = tid >> 5, lane = tid & 31;
    int wm = warp & 3, wn = warp >> 2;
    int tg = lane & 3, gp = lane >> 2;
    int mb = wm * 16;
    float acc[16][4] = {};
    for (int kt = 0; kt < 256; kt += 16) {
        {
            int row = tid >> 2, k4 = (tid & 3) * 4;
            float4 v = *(const float4*)&A[(size_t)(m0+row)*256 + kt + k4];
            sA[row][k4+0]=f2tf(v.x); sA[row][k4+1]=f2tf(v.y);
            sA[row][k4+2]=f2tf(v.z); sA[row][k4+3]=f2tf(v.w);
        }
        {
            const float* wrow = Wm + (size_t)tid*256 + kt;
            #pragma unroll
            for (int i = 0; i < 4; i++) {
                float4 w = *(const float4*)&wrow[i*4];
                sB[i*4+0][tid]=f2tf(w.x); sB[i*4+1][tid]=f2tf(w.y);
                sB[i*4+2][tid]=f2tf(w.z); sB[i*4+3][tid]=f2tf(w.w);
            }
        }
        __syncthreads();
        #pragma unroll
        for (int k0 = 0; k0 < 16; k0 += 8) {
            unsigned a0 = sA[mb+gp  ][k0+tg],   a1 = sA[mb+8+gp][k0+tg];
            unsigned a2 = sA[mb+gp  ][k0+tg+4], a3 = sA[mb+8+gp][k0+tg+4];
            #pragma unroll
            for (int n8 = 0; n8 < 16; n8++) {
                unsigned b0 = sB[k0+tg  ][wn*128 + n8*8+gp];
                unsigned b1 = sB[k0+tg+4][wn*128 + n8*8+gp];
                mma_tf32(acc[n8], a0, a1, a2, a3, b0, b1);
            }
        }
        __syncthreads();
    }
    int gm0 = m0 + mb + gp, gm1 = gm0 + 8;
    #pragma unroll
    for (int n8 = 0; n8 < 16; n8++) {
        int gn = wn*128 + n8*8 + tg*2;
        float b0 = bias[gn], b1 = bias[gn+1];
        float v0 = acc[n8][0] + b0, v1 = acc[n8][1] + b1;
        float v2 = acc[n8][2] + b0, v3 = acc[n8][3] + b1;
        *(float2*)&g_q[(size_t)gm0*DD + gn] = make_float2(v0, v1);
        *(float2*)&g_q[(size_t)gm1*DD + gn] = make_float2(v2, v3);
        *(half2*)&g_qh[(size_t)gm0*DD + gn] = __floats2half2_rn(v0, v1);
        *(half2*)&g_qh[(size_t)gm1*DD + gn] = __floats2half2_rn(v2, v3);
    }
}

/* ------ phases via separable axis factors; also zeroes edge counters ------- */
__global__ void k_phase(const float* __restrict__ pos, const float* __restrict__ cell) {
    __shared__ float er[3][13], ei[3][13];
    int bn = blockIdx.x;
    int b  = bn / NA;
    int tid = threadIdx.x;
    if (tid == 64) g_cnt[bn] = 0;
    if (tid == 96) g_fil[bn] = 0;
    float px = pos[bn*3+0], py = pos[bn*3+1], pz = pos[bn*3+2];
    if (tid < 39) {
        float iM[9], ad;
        cell_inv(cell + b*9, iM, &ad);
        int axis = tid / 13, idx = tid % 13;
        float u;
        if      (axis == 0) u = iM[0]*px + iM[3]*py + iM[6]*pz;
        else if (axis == 1) u = iM[1]*px + iM[4]*py + iM[7]*pz;
        else                u = iM[2]*px + iM[5]*py + iM[8]*pz;
        float ph = 2.0f*PI_F * u * (float)(idx - 6);
        float s, c; __sincosf(ph, &s, &c);
        er[axis][idx] = c; ei[axis][idx] = s;
    }
    __syncthreads();
    size_t base = (size_t)bn * KP;
    for (int k2 = tid; k2 < KP/2; k2 += 256) {
        int k = k2 * 2;
        float c0=0.f, s0=0.f, c1=0.f, s1=0.f;
        #pragma unroll
        for (int h = 0; h < 2; h++) {
            int m = k + h;
            if (m < KNUMH) {
                int i = m / 169; int r = m - i*169;
                int j = r / 13;  int l = r - j*13;
                float ar = er[0][i], ai = ei[0][i];
                float br = er[1][j], bi = ei[1][j];
                float tr = ar*br - ai*bi, ti = ar*bi + ai*br;
                float cr = er[2][l], ci = ei[2][l];
                float cc = tr*cr - ti*ci, ss = tr*ci + ti*cr;
                if (h == 0) { c0 = cc; s0 = ss; } else { c1 = cc; s1 = ss; }
            }
        }
        *(half2*)&g_cosh[base + k] = __floats2half2_rn(c0, c1);
        *(half2*)&g_sinh[base + k] = __floats2half2_rn(s0, s1);
    }
}

/* ---------------- edge pipeline: count -> scan -> fill -> gather ----------- */
__global__ void k_count(const int* __restrict__ nbidx) {
    int e = blockIdx.x * blockDim.x + threadIdx.x;
    if (e >= BB*EE) return;
    int b = e / EE;
    int i = nbidx[e*2];
    atomicAdd(&g_cnt[b*NA + i], 1);
}

__global__ void k_scan() {
    __shared__ int s[2048];
    int b = blockIdx.x, tid = threadIdx.x;
    #pragma unroll
    for (int i = 0; i < 2; i++) {
        int idx = tid + i*1024;
        s[idx] = (idx < NA) ? g_cnt[b*NA + idx] : 0;
    }
    int offset = 1;
    for (int d = 1024; d > 0; d >>= 1) {
        __syncthreads();
        if (tid < d) {
            int ai = offset*(2*tid+1) - 1;
            int bi = offset*(2*tid+2) - 1;
            s[bi] += s[ai];
        }
        offset <<= 1;
    }
    if (tid == 0) s[2047] = 0;
    for (int d = 1; d < 2048; d <<= 1) {
        offset >>= 1;
        __syncthreads();
        if (tid < d) {
            int ai = offset*(2*tid+1) - 1;
            int bi = offset*(2*tid+2) - 1;
            int t = s[ai]; s[ai] = s[bi]; s[bi] += t;
        }
    }
    __syncthreads();
    #pragma unroll
    for (int i = 0; i < 2; i++) {
        int idx = tid + i*1024;
        if (idx < NA) g_off[b*NA + idx] = s[idx];
    }
}

__global__ void k_fill(const int* __restrict__ nbidx, const float* __restrict__ nbdist) {
    int e = blockIdx.x * blockDim.x + threadIdx.x;
    if (e >= BB*EE) return;
    int b = e / EE;
    int i = nbidx[e*2 + 0];
    int j = nbidx[e*2 + 1];
    float d = nbdist[e];
    float v  = erfcf(d * 0.70710678118f) / d;
    float fc = (d < 5.0f) ? 0.5f*(__cosf(PI_F * d * 0.2f) + 1.0f) : 0.0f;
    float vsr = v - fc / d;
    int pos = g_off[b*NA + i] + atomicAdd(&g_fil[b*NA + i], 1);
    g_elj[b*EE + pos] = j;
    g_elv[b*EE + pos] = vsr;
}

/* 128 threads: 4 warps x 4 concurrent edges, uint4 (8-chan) loads,
   cross-warp smem reduction. */
__global__ void k_gather() {
    __shared__ float red[4][256];
    int bn = blockIdx.x;
    int b  = bn / NA;
    int tid = threadIdx.x, warp = tid >> 5, lane = tid & 31;
    int start = g_off[bn];
    int cnt   = g_cnt[bn];
    const int*   ej = g_elj + b*EE + start;
    const float* ev = g_elv + b*EE + start;
    const uint4* qb = (const uint4*)(g_qh + (size_t)b*NA*DD);   /* 32 uint4/row */
    float acc[8] = {};
    for (int e = warp; e < cnt; e += 4) {
        int   j = ej[e];
        float v = ev[e];
        uint4 u = qb[(size_t)j*32 + lane];
        half2* h = (half2*)&u;
        #pragma unroll
        for (int p = 0; p < 4; p++) {
            float2 f = __half22float2(h[p]);
            acc[2*p]   += v * f.x;
            acc[2*p+1] += v * f.y;
        }
    }
    #pragma unroll
    for (int p = 0; p < 8; p++) red[warp][lane*8 + p] = acc[p];
    __syncthreads();
    int c = tid * 2;
    float s0 = red[0][c]   + red[1][c]   + red[2][c]   + red[3][c];
    float s1 = red[0][c+1] + red[1][c+1] + red[2][c+1] + red[3][c+1];
    *(float2*)&g_pot[(size_t)bn*DD + c] = make_float2(s0, s1);
}

/* ---------------- fp16 TN fused: Sc = G*(c^T q), Ss = G*(s^T q) ------------ */
/* grid (9, 2, 8), 256 threads, 8 warps 4m x 2n. tile 128m x 128n, kt 32. */
#define SF_SST 8704                 /* one stage of one array: 32*136*2 bytes */
#define SF_SC 0
#define SF_SS (2*SF_SST)
#define SF_SQ (4*SF_SST)
#define SF_SMEM (6*SF_SST)          /* 52224 */

__global__ void __launch_bounds__(256, 1) k_sf(const float* __restrict__ cell) {
    extern __shared__ __align__(16) char smem[];
    unsigned sb = sptr(smem);
    int b  = blockIdx.z;
    int m0 = blockIdx.x * 128;
    int n0 = blockIdx.y * 128;
    int tid = threadIdx.x, warp = tid >> 5, lane = tid & 31;
    int wm = warp & 3, wn = warp >> 2;
    int tg = lane & 3, gp = lane >> 2;
    const half* cosb = g_cosh + (size_t)b * NA * KP;
    const half* sinb = g_sinh + (size_t)b * NA * KP;
    const half* qb   = g_qh   + (size_t)b * NA * DD;
    float accC[2][8][4] = {}, accS[2][8][4] = {};
    int r0 = tid >> 4, lc8 = (tid & 15) * 8;
    unsigned w0 = (unsigned)(r0*272 + lc8*2);
    unsigned w1 = w0 + 16*272;
    const half* pc0 = cosb + (size_t)r0*KP + m0 + lc8;
    const half* ps0 = sinb + (size_t)r0*KP + m0 + lc8;
    const half* pq0 = qb   + (size_t)r0*DD + n0 + lc8;
    int arow = (lane & 7) + ((lane >> 4) << 3);
    unsigned aAcO[2], aAsO[2], aBqO[4];
    #pragma unroll
    for (int f = 0; f < 2; f++) {
        int acol = wm*32 + f*16 + ((lane >> 3) & 1) * 8;
        aAcO[f] = SF_SC + (unsigned)(arow*272 + acol*2);
        aAsO[f] = SF_SS + (unsigned)(arow*272 + acol*2);
    }
    int brow = lane & 15, bc8 = ((lane >> 4) << 3);
    #pragma unroll
    for (int p = 0; p < 4; p++)
        aBqO[p] = SF_SQ + (unsigned)(brow*272 + (wn*64 + p*16 + bc8)*2);

    #define SF_LOAD(t, stage, sz1) do {                                       \
        unsigned so_ = (stage)*SF_SST;                                        \
        size_t ro_ = (size_t)(t)*32;                                          \
        CPA16 (sb + SF_SC + so_ + w0, pc0 + ro_*KP);                          \
        CPA16Z(sb + SF_SC + so_ + w1, pc0 + (ro_+16)*KP, sz1);                \
        CPA16 (sb + SF_SS + so_ + w0, ps0 + ro_*KP);                          \
        CPA16Z(sb + SF_SS + so_ + w1, ps0 + (ro_+16)*KP, sz1);                \
        CPA16 (sb + SF_SQ + so_ + w0, pq0 + ro_*DD);                          \
        CPA16Z(sb + SF_SQ + so_ + w1, pq0 + (ro_+16)*DD, sz1);                \
    } while (0)

    const int NT = (NA + 31) / 32;   /* 63; tail rows zero-filled */
    SF_LOAD(0, 0, 16); CPCOMMIT();
    SF_LOAD(1, 1, 16); CPCOMMIT();
    for (int t = 0; t < NT; t++) {
        CPWAIT1();
        __syncthreads();
        unsigned so = (t & 1) * SF_SST;
        #pragma unroll
        for (int kk2 = 0; kk2 < 2; kk2++) {
            unsigned off = sb + so + kk2*(16*272);
            unsigned af[2][4], sf_[2][4];
            ldsm4t(af[0],  aAcO[0]+off); ldsm4t(af[1],  aAcO[1]+off);
            ldsm4t(sf_[0], aAsO[0]+off); ldsm4t(sf_[1], aAsO[1]+off);
            #pragma unroll
            for (int p = 0; p < 4; p++) {
                unsigned bq[4]; ldsm4t(bq, aBqO[p]+off);
                #pragma unroll
                for (int f = 0; f < 2; f++) {
                    mma16816(accC[f][2*p  ], af[f],  bq[0], bq[1]);
                    mma16816(accC[f][2*p+1], af[f],  bq[2], bq[3]);
                    mma16816(accS[f][2*p  ], sf_[f], bq[0], bq[1]);
                    mma16816(accS[f][2*p+1], sf_[f], bq[2], bq[3]);
                }
            }
        }
        __syncthreads();
        if (t + 2 < NT) {
            int sz1 = (t + 2 == NT - 1) ? 0 : 16;
            SF_LOAD(t+2, t & 1, sz1);
        }
        CPCOMMIT();
    }
    float iM[9], ad;
    cell_inv(cell + b*9, iM, &ad);
    #pragma unroll
    for (int f = 0; f < 2; f++) {
        int gm0 = m0 + wm*32 + f*16 + gp, gm1 = gm0 + 8;
        float G0 = green_eval(gm0, iM, ad);
        float G1 = green_eval(gm1, iM, ad);
        #pragma unroll
        for (int nf = 0; nf < 8; nf++) {
            int gn = n0 + wn*64 + nf*8 + tg*2;
            *(half2*)&g_Sch[(size_t)(b*KP+gm0)*DD + gn] = __floats2half2_rn(G0*accC[f][nf][0], G0*accC[f][nf][1]);
            *(half2*)&g_Sch[(size_t)(b*KP+gm1)*DD + gn] = __floats2half2_rn(G1*accC[f][nf][2], G1*accC[f][nf][3]);
            *(half2*)&g_Ssh[(size_t)(b*KP+gm0)*DD + gn] = __floats2half2_rn(G0*accS[f][nf][0], G0*accS[f][nf][1]);
            *(half2*)&g_Ssh[(size_t)(b*KP+gm1)*DD + gn] = __floats2half2_rn(G1*accS[f][nf][2], G1*accS[f][nf][3]);
        }
    }
}

/* ---------------- fp16 NN fused + epilogue: out = (pot+acc+Cq)q ------------ */
/* grid (16, 2, 8), 256 threads, 8 warps 4m x 2n, occ 2, kt 32, 2-stage. */
#define KT_SSA 10240                /* A stage: 128*40*2 */
#define KT_SSB 8704                 /* B stage: 32*136*2 */
#define KT_AC 0
#define KT_AS (2*KT_SSA)
#define KT_BC (4*KT_SSA)
#define KT_BS (KT_BC + 2*KT_SSB)
#define KT_SMEM (KT_BS + 2*KT_SSB)  /* 75776 */

__global__ void __launch_bounds__(256, 2) k_pot(float* __restrict__ out) {
    extern __shared__ __align__(16) char smem[];
    unsigned sb = sptr(smem);
    int b  = blockIdx.z;
    int m0 = blockIdx.x * 128;
    int n0 = blockIdx.y * 128;
    int tid = threadIdx.x, warp = tid >> 5, lane = tid & 31;
    int wm = warp & 3, wn = warp >> 2;
    int tg = lane & 3, gp = lane >> 2;
    const half* cosb = g_cosh + (size_t)b * NA * KP;
    const half* sinb = g_sinh + (size_t)b * NA * KP;
    float acc[2][8][4] = {};
    int rowA = tid >> 1, cA8 = (tid & 1) * 8;
    int srcA = (m0 + rowA) < NA ? 16 : 0;
    int rowAc = (m0 + rowA) < NA ? (m0 + rowA) : (NA - 1);
    unsigned wA0 = (unsigned)(rowA*80 + cA8*2);
    unsigned wA1 = wA0 + 32;
    const half* pAc = cosb + (size_t)rowAc*KP + cA8;
    const half* pAs = sinb + (size_t)rowAc*KP + cA8;
    int rowB = tid >> 4, cB8 = (tid & 15) * 8;
    unsigned wB0 = (unsigned)(rowB*272 + cB8*2);
    unsigned wB1 = wB0 + 16*272;
    const half* pBc = g_Sch + (size_t)((size_t)b*KP + rowB)*DD + n0 + cB8;
    const half* pBs = g_Ssh + (size_t)((size_t)b*KP + rowB)*DD + n0 + cB8;
    int r = lane & 7, g = lane >> 3;
    unsigned aAO[2], aSO[2], aBcO[4], aBsO[4];
    #pragma unroll
    for (int f = 0; f < 2; f++) {
        int rr = wm*32 + f*16 + r + (g & 1)*8;
        int cc = (g >> 1) * 8;
        aAO[f] = KT_AC + (unsigned)(rr*80 + cc*2);
        aSO[f] = KT_AS + (unsigned)(rr*80 + cc*2);
    }
    int brow = lane & 15, bc8 = ((lane >> 4) << 3);
    #pragma unroll
    for (int p = 0; p < 4; p++) {
        aBcO[p] = KT_BC + (unsigned)(brow*272 + (wn*64 + p*16 + bc8)*2);
        aBsO[p] = KT_BS + (unsigned)(brow*272 + (wn*64 + p*16 + bc8)*2);
    }

    #define KT_LOAD(t, stage) do {                                            \
        unsigned sa_ = (stage)*KT_SSA, sbo_ = (stage)*KT_SSB;                 \
        size_t ko_ = (size_t)(t)*32;                                          \
        CPA16Z(sb + KT_AC + sa_ + wA0, pAc + ko_,      srcA);                 \
        CPA16Z(sb + KT_AC + sa_ + wA1, pAc + ko_ + 16, srcA);                 \
        CPA16Z(sb + KT_AS + sa_ + wA0, pAs + ko_,      srcA);                 \
        CPA16Z(sb + KT_AS + sa_ + wA1, pAs + ko_ + 16, srcA);                 \
        CPA16 (sb + KT_BC + sbo_ + wB0, pBc + ko_*DD);                        \
        CPA16 (sb + KT_BC + sbo_ + wB1, pBc + (ko_+16)*DD);                   \
        CPA16 (sb + KT_BS + sbo_ + wB0, pBs + ko_*DD);                        \
        CPA16 (sb + KT_BS + sbo_ + wB1, pBs + (ko_+16)*DD);                   \
    } while (0)

    const int NT = KP / 32;   /* 36 exact */
    KT_LOAD(0, 0); CPCOMMIT();
    KT_LOAD(1, 1); CPCOMMIT();
    for (int t = 0; t < NT; t++) {
        CPWAIT1();
        __syncthreads();
        unsigned sa = (t & 1) * KT_SSA, sbo = (t & 1) * KT_SSB;
        #pragma unroll
        for (int kk2 = 0; kk2 < 2; kk2++) {
            unsigned aoff = sb + sa + kk2*32;
            unsigned boff = sb + sbo + kk2*(16*272);
            unsigned af[2][4], sf_[2][4];
            ldsm4(af[0],  aAO[0]+aoff); ldsm4(af[1],  aAO[1]+aoff);
            ldsm4(sf_[0], aSO[0]+aoff); ldsm4(sf_[1], aSO[1]+aoff);
            #pragma unroll
            for (int p = 0; p < 4; p++) {
                unsigned bb[4];
                ldsm4t(bb, aBcO[p]+boff);
                #pragma unroll
                for (int f = 0; f < 2; f++) {
                    mma16816(acc[f][2*p  ], af[f], bb[0], bb[1]);
                    mma16816(acc[f][2*p+1], af[f], bb[2], bb[3]);
                }
                ldsm4t(bb, aBsO[p]+boff);
                #pragma unroll
                for (int f = 0; f < 2; f++) {
                    mma16816(acc[f][2*p  ], sf_[f], bb[0], bb[1]);
                    mma16816(acc[f][2*p+1], sf_[f], bb[2], bb[3]);
                }
            }
        }
        __syncthreads();
        if (t + 2 < NT) KT_LOAD(t+2, t & 1);
        CPCOMMIT();
    }
    #pragma unroll
    for (int f = 0; f < 2; f++) {
        int gm0 = m0 + wm*32 + f*16 + gp, gm1 = gm0 + 8;
        #pragma unroll
        for (int nf = 0; nf < 8; nf++) {
            int gn = n0 + wn*64 + nf*8 + tg*2;
            if (gm0 < NA) {
                size_t idx = (size_t)(b*NA+gm0)*DD + gn;
                float2 pr = *(const float2*)&g_pot[idx];
                float2 qv = *(const float2*)&g_q[idx];
                float2 o;
                o.x = (pr.x + acc[f][nf][0] + C_SELF*qv.x) * qv.x;
                o.y = (pr.y + acc[f][nf][1] + C_SELF*qv.y) * qv.y;
                *(float2*)&out[idx] = o;
            }
            if (gm1 < NA) {
                size_t idx = (size_t)(b*NA+gm1)*DD + gn;
                float2 pr = *(const float2*)&g_pot[idx];
                float2 qv = *(const float2*)&g_q[idx];
                float2 o;
                o.x = (pr.x + acc[f][nf][2] + C_SELF*qv.x) * qv.x;
                o.y = (pr.y + acc[f][nf][3] + C_SELF*qv.y) * qv.y;
                *(float2*)&out[idx] = o;
            }
        }
    }
}

/* ---------------- launch -------------------------------------------------- */
/* Order chosen so the 4th launch (the one ncu captures) is k_sf. */
extern "C" void kernel_launch(void* const* d_in, const int* in_sizes, int n_in,
                              void* d_out, int out_size) {
    const float* features = (const float*)d_in[0];
    const float* positions= (const float*)d_in[1];
    const float* cell     = (const float*)d_in[2];
    const int*   nbidx    = (const int*)  d_in[3];
    const float* nbdist   = (const float*)d_in[4];
    const float* W        = (const float*)d_in[5];
    const float* bias     = (const float*)d_in[6];
    float* out = (float*)d_out;

    cudaFuncSetAttribute(k_sf,  cudaFuncAttributeMaxDynamicSharedMemorySize, SF_SMEM);
    cudaFuncSetAttribute(k_pot, cudaFuncAttributeMaxDynamicSharedMemorySize, KT_SMEM);

    k_phase  <<<BB*NA, 256>>>(positions, cell);
    k_charges<<<(BB*NA)/64, 256>>>(features, W, bias);
    k_count  <<<(BB*EE+255)/256, 256>>>(nbidx);
    k_sf     <<<dim3(KP/128, DD/128, BB), 256, SF_SMEM>>>(cell);
    k_scan   <<<BB, 1024>>>();
    k_fill   <<<(BB*EE+255)/256, 256>>>(nbidx, nbdist);
    k_gather <<<BB*NA, 128>>>();
    k_pot    <<<dim3((NA+127)/128, DD/128, BB), 256, KT_SMEM>>>(out);
    (void)in_sizes; (void)n_in; (void)out_size;
}

// round 14
// speedup vs baseline: 1.0456x; 1.0456x over previous
#include <cuda_runtime.h>
#include <cuda_fp16.h>
#include <stdint.h>
#include <math.h>

#define BB 8
#define NA 2000
#define DD 256
#define EE 64000
#define KNUMH 1098       /* half-space k-vectors (m = 0..1097) */
#define KP 1152          /* 128 * 9, padded with G=0, cos/sin=0 */
#define PI_F 3.14159265358979f
#define C_SELF (-0.7978845608028654f)   /* -sqrt(2/pi)/sigma */

/* ---------------- scratch (device globals; no allocations allowed) -------- */
__device__ float g_q  [BB*NA*DD];
__device__ float g_pot[BB*NA*DD];
__device__ __align__(16) half g_qh  [BB*NA*DD];
__device__ __align__(16) half g_cosh[(size_t)BB*NA*KP];
__device__ __align__(16) half g_sinh[(size_t)BB*NA*KP];
__device__ __align__(16) half g_Sch [BB*KP*DD];
__device__ __align__(16) half g_Ssh [BB*KP*DD];
__device__ int   g_cnt[BB*NA];
__device__ int   g_off[BB*NA];
__device__ int   g_fil[BB*NA];
__device__ int   g_elj[BB*EE];
__device__ float g_elv[BB*EE];

/* ---------------- MMA / ldmatrix / cp.async helpers ------------------------ */
__device__ __forceinline__ unsigned sptr(const void* p) {
    return (unsigned)__cvta_generic_to_shared(p);
}
__device__ __forceinline__ void ldsm4(unsigned* r, unsigned a) {
    asm volatile("ldmatrix.sync.aligned.m8n8.x4.shared.b16 {%0,%1,%2,%3},[%4];"
        : "=r"(r[0]), "=r"(r[1]), "=r"(r[2]), "=r"(r[3]) : "r"(a));
}
__device__ __forceinline__ void ldsm4t(unsigned* r, unsigned a) {
    asm volatile("ldmatrix.sync.aligned.m8n8.x4.trans.shared.b16 {%0,%1,%2,%3},[%4];"
        : "=r"(r[0]), "=r"(r[1]), "=r"(r[2]), "=r"(r[3]) : "r"(a));
}
__device__ __forceinline__ void mma16816(float* d, const unsigned* a,
                                         unsigned b0, unsigned b1) {
    asm volatile(
        "mma.sync.aligned.m16n8k16.row.col.f32.f16.f16.f32 "
        "{%0,%1,%2,%3},{%4,%5,%6,%7},{%8,%9},{%0,%1,%2,%3};"
        : "+f"(d[0]), "+f"(d[1]), "+f"(d[2]), "+f"(d[3])
        : "r"(a[0]), "r"(a[1]), "r"(a[2]), "r"(a[3]), "r"(b0), "r"(b1));
}
__device__ __forceinline__ unsigned f2tf(float x) {
    unsigned r; asm("cvt.rna.tf32.f32 %0, %1;" : "=r"(r) : "f"(x)); return r;
}
__device__ __forceinline__ void mma_tf32(float* d, unsigned a0, unsigned a1,
                                         unsigned a2, unsigned a3,
                                         unsigned b0, unsigned b1) {
    asm volatile(
        "mma.sync.aligned.m16n8k8.row.col.f32.tf32.tf32.f32 "
        "{%0,%1,%2,%3},{%4,%5,%6,%7},{%8,%9},{%0,%1,%2,%3};"
        : "+f"(d[0]), "+f"(d[1]), "+f"(d[2]), "+f"(d[3])
        : "r"(a0), "r"(a1), "r"(a2), "r"(a3), "r"(b0), "r"(b1));
}
#define CPA16(d, s)     asm volatile("cp.async.ca.shared.global [%0], [%1], 16;" :: "r"(d), "l"(s))
#define CPA16Z(d, s, n) asm volatile("cp.async.ca.shared.global [%0], [%1], 16, %2;" :: "r"(d), "l"(s), "r"(n))
#define CPCOMMIT()      asm volatile("cp.async.commit_group;")
#define CPWAIT1()       asm volatile("cp.async.wait_group 1;")

/* ---------------- Green's function evaluation (inline) --------------------- */
__device__ __forceinline__ void cell_inv(const float* C, float* iM, float* absdet) {
    float c00=C[0],c01=C[1],c02=C[2];
    float c10=C[3],c11=C[4],c12=C[5];
    float c20=C[6],c21=C[7],c22=C[8];
    float det = c00*(c11*c22-c12*c21) - c01*(c10*c22-c12*c20) + c02*(c10*c21-c11*c20);
    float id = 1.0f/det;
    iM[0]=(c11*c22-c12*c21)*id; iM[1]=(c02*c21-c01*c22)*id; iM[2]=(c01*c12-c02*c11)*id;
    iM[3]=(c12*c20-c10*c22)*id; iM[4]=(c00*c22-c02*c20)*id; iM[5]=(c02*c10-c00*c12)*id;
    iM[6]=(c10*c21-c11*c20)*id; iM[7]=(c01*c20-c00*c21)*id; iM[8]=(c00*c11-c01*c10)*id;
    *absdet = fabsf(det);
}
__device__ __forceinline__ float green_eval(int k, const float* iM, float absdet) {
    if (k >= KNUMH) return 0.f;
    float ni = (float)(k/169 - 6);
    float nj = (float)((k/13)%13 - 6);
    float nk = (float)(k%13 - 6);
    float kx = 2.0f*PI_F*(iM[0]*ni + iM[1]*nj + iM[2]*nk);
    float ky = 2.0f*PI_F*(iM[3]*ni + iM[4]*nj + iM[5]*nk);
    float kz = 2.0f*PI_F*(iM[6]*ni + iM[7]*nj + iM[8]*nk);
    float k2 = kx*kx + ky*ky + kz*kz;
    return 8.0f*PI_F/absdet * __expf(-0.5f*k2) / k2;   /* x2 for ±k pair */
}

/* ---------------- charges = features @ W^T + b (tf32 MMA) ------------------ */
/* grid (250, 4), 128 threads. tiles 64m x 64n, kt 16.  (R11 proven version) */
__global__ void k_charges(const float* __restrict__ A, const float* __restrict__ Wm,
                          const float* __restrict__ bias) {
    __shared__ unsigned sA[64][20];
    __shared__ unsigned sB[16][72];
    int m0 = blockIdx.x * 64, n0 = blockIdx.y * 64;
    int tid = threadIdx.x, warp = tid >> 5, lane = tid & 31;
    int tg = lane & 3, gp = lane >> 2;
    int mb = warp * 16;
    float acc[8][4] = {};
    for (int kt = 0; kt < 256; kt += 16) {
        #pragma unroll
        for (int i = 0; i < 2; i++) {
            int t = tid + i*128;
            int row = t >> 2, k4 = (t & 3) * 4;
            float4 v = *(const float4*)&A[(size_t)(m0+row)*256 + kt + k4];
            sA[row][k4+0]=f2tf(v.x); sA[row][k4+1]=f2tf(v.y);
            sA[row][k4+2]=f2tf(v.z); sA[row][k4+3]=f2tf(v.w);
            float4 w = *(const float4*)&Wm[(size_t)(n0+row)*256 + kt + k4];
            sB[k4+0][row]=f2tf(w.x); sB[k4+1][row]=f2tf(w.y);
            sB[k4+2][row]=f2tf(w.z); sB[k4+3][row]=f2tf(w.w);
        }
        __syncthreads();
        #pragma unroll
        for (int k0 = 0; k0 < 16; k0 += 8) {
            unsigned a0 = sA[mb+gp  ][k0+tg],   a1 = sA[mb+8+gp][k0+tg];
            unsigned a2 = sA[mb+gp  ][k0+tg+4], a3 = sA[mb+8+gp][k0+tg+4];
            #pragma unroll
            for (int n8 = 0; n8 < 8; n8++) {
                unsigned b0 = sB[k0+tg  ][n8*8+gp];
                unsigned b1 = sB[k0+tg+4][n8*8+gp];
                mma_tf32(acc[n8], a0, a1, a2, a3, b0, b1);
            }
        }
        __syncthreads();
    }
    int gm0 = m0 + mb + gp, gm1 = gm0 + 8;
    #pragma unroll
    for (int n8 = 0; n8 < 8; n8++) {
        int gn = n0 + n8*8 + tg*2;
        float b0 = bias[gn], b1 = bias[gn+1];
        float v0 = acc[n8][0] + b0, v1 = acc[n8][1] + b1;
        float v2 = acc[n8][2] + b0, v3 = acc[n8][3] + b1;
        *(float2*)&g_q[(size_t)gm0*DD + gn] = make_float2(v0, v1);
        *(float2*)&g_q[(size_t)gm1*DD + gn] = make_float2(v2, v3);
        *(half2*)&g_qh[(size_t)gm0*DD + gn] = __floats2half2_rn(v0, v1);
        *(half2*)&g_qh[(size_t)gm1*DD + gn] = __floats2half2_rn(v2, v3);
    }
}

/* ------ phases via separable axis factors; also zeroes edge counters ------- */
__global__ void k_phase(const float* __restrict__ pos, const float* __restrict__ cell) {
    __shared__ float er[3][13], ei[3][13];
    int bn = blockIdx.x;
    int b  = bn / NA;
    int tid = threadIdx.x;
    if (tid == 64) g_cnt[bn] = 0;
    if (tid == 96) g_fil[bn] = 0;
    float px = pos[bn*3+0], py = pos[bn*3+1], pz = pos[bn*3+2];
    if (tid < 39) {
        float iM[9], ad;
        cell_inv(cell + b*9, iM, &ad);
        int axis = tid / 13, idx = tid % 13;
        float u;
        if      (axis == 0) u = iM[0]*px + iM[3]*py + iM[6]*pz;
        else if (axis == 1) u = iM[1]*px + iM[4]*py + iM[7]*pz;
        else                u = iM[2]*px + iM[5]*py + iM[8]*pz;
        float ph = 2.0f*PI_F * u * (float)(idx - 6);
        float s, c; __sincosf(ph, &s, &c);
        er[axis][idx] = c; ei[axis][idx] = s;
    }
    __syncthreads();
    size_t base = (size_t)bn * KP;
    for (int k2 = tid; k2 < KP/2; k2 += 256) {
        int k = k2 * 2;
        float c0=0.f, s0=0.f, c1=0.f, s1=0.f;
        #pragma unroll
        for (int h = 0; h < 2; h++) {
            int m = k + h;
            if (m < KNUMH) {
                int i = m / 169; int r = m - i*169;
                int j = r / 13;  int l = r - j*13;
                float ar = er[0][i], ai = ei[0][i];
                float br = er[1][j], bi = ei[1][j];
                float tr = ar*br - ai*bi, ti = ar*bi + ai*br;
                float cr = er[2][l], ci = ei[2][l];
                float cc = tr*cr - ti*ci, ss = tr*ci + ti*cr;
                if (h == 0) { c0 = cc; s0 = ss; } else { c1 = cc; s1 = ss; }
            }
        }
        *(half2*)&g_cosh[base + k] = __floats2half2_rn(c0, c1);
        *(half2*)&g_sinh[base + k] = __floats2half2_rn(s0, s1);
    }
}

/* ---------------- edge pipeline: count -> scan -> fill -> gather ----------- */
__global__ void k_count(const int* __restrict__ nbidx) {
    int e = blockIdx.x * blockDim.x + threadIdx.x;
    if (e >= BB*EE) return;
    int b = e / EE;
    int i = nbidx[e*2];
    atomicAdd(&g_cnt[b*NA + i], 1);
}

__global__ void k_scan() {
    __shared__ int s[2048];
    int b = blockIdx.x, tid = threadIdx.x;
    #pragma unroll
    for (int i = 0; i < 2; i++) {
        int idx = tid + i*1024;
        s[idx] = (idx < NA) ? g_cnt[b*NA + idx] : 0;
    }
    int offset = 1;
    for (int d = 1024; d > 0; d >>= 1) {
        __syncthreads();
        if (tid < d) {
            int ai = offset*(2*tid+1) - 1;
            int bi = offset*(2*tid+2) - 1;
            s[bi] += s[ai];
        }
        offset <<= 1;
    }
    if (tid == 0) s[2047] = 0;
    for (int d = 1; d < 2048; d <<= 1) {
        offset >>= 1;
        __syncthreads();
        if (tid < d) {
            int ai = offset*(2*tid+1) - 1;
            int bi = offset*(2*tid+2) - 1;
            int t = s[ai]; s[ai] = s[bi]; s[bi] += t;
        }
    }
    __syncthreads();
    #pragma unroll
    for (int i = 0; i < 2; i++) {
        int idx = tid + i*1024;
        if (idx < NA) g_off[b*NA + idx] = s[idx];
    }
}

__global__ void k_fill(const int* __restrict__ nbidx, const float* __restrict__ nbdist) {
    int e = blockIdx.x * blockDim.x + threadIdx.x;
    if (e >= BB*EE) return;
    int b = e / EE;
    int i = nbidx[e*2 + 0];
    int j = nbidx[e*2 + 1];
    float d = nbdist[e];
    float v  = erfcf(d * 0.70710678118f) / d;
    float fc = (d < 5.0f) ? 0.5f*(__cosf(PI_F * d * 0.2f) + 1.0f) : 0.0f;
    float vsr = v - fc / d;
    int pos = g_off[b*NA + i] + atomicAdd(&g_fil[b*NA + i], 1);
    g_elj[b*EE + pos] = j;
    g_elv[b*EE + pos] = vsr;
}

/* 128 threads: 4 warps x 4 concurrent edges, uint4 (8-chan) loads,
   cross-warp smem reduction. */
__global__ void k_gather() {
    __shared__ float red[4][256];
    int bn = blockIdx.x;
    int b  = bn / NA;
    int tid = threadIdx.x, warp = tid >> 5, lane = tid & 31;
    int start = g_off[bn];
    int cnt   = g_cnt[bn];
    const int*   ej = g_elj + b*EE + start;
    const float* ev = g_elv + b*EE + start;
    const uint4* qb = (const uint4*)(g_qh + (size_t)b*NA*DD);   /* 32 uint4/row */
    float acc[8] = {};
    for (int e = warp; e < cnt; e += 4) {
        int   j = ej[e];
        float v = ev[e];
        uint4 u = qb[(size_t)j*32 + lane];
        half2* h = (half2*)&u;
        #pragma unroll
        for (int p = 0; p < 4; p++) {
            float2 f = __half22float2(h[p]);
            acc[2*p]   += v * f.x;
            acc[2*p+1] += v * f.y;
        }
    }
    #pragma unroll
    for (int p = 0; p < 8; p++) red[warp][lane*8 + p] = acc[p];
    __syncthreads();
    int c = tid * 2;
    float s0 = red[0][c]   + red[1][c]   + red[2][c]   + red[3][c];
    float s1 = red[0][c+1] + red[1][c+1] + red[2][c+1] + red[3][c+1];
    *(float2*)&g_pot[(size_t)bn*DD + c] = make_float2(s0, s1);
}

/* ---------------- fp16 TN: S{c|s} = G*(ph^T q), cos/sin split -------------- */
/* grid (9, 4, 8): y = (cs<<1)|n-tile. 256 threads, 8 warps 4m x 2n.         */
/* tile 128m x 128n, kt 32, 2-stage cp.async, occ 2.                          */
#define SF_SST 8704                 /* one stage of one array: 32*136*2 bytes */
#define SF_SA 0
#define SF_SQ (2*SF_SST)
#define SF_SMEM (4*SF_SST)          /* 34816 */

__global__ void __launch_bounds__(256, 2) k_sf(const float* __restrict__ cell) {
    extern __shared__ __align__(16) char smem[];
    unsigned sb = sptr(smem);
    int b  = blockIdx.z;
    int m0 = blockIdx.x * 128;
    int yb = blockIdx.y;
    int n0 = (yb & 1) * 128;
    int cs = yb >> 1;                       /* 0 = cos->Sc, 1 = sin->Ss */
    int tid = threadIdx.x, warp = tid >> 5, lane = tid & 31;
    int wm = warp & 3, wn = warp >> 2;
    int tg = lane & 3, gp = lane >> 2;
    const half* phb = (cs ? g_sinh : g_cosh) + (size_t)b * NA * KP;
    const half* qb  = g_qh + (size_t)b * NA * DD;
    half* Sout = (cs ? g_Ssh : g_Sch);
    float acc[2][8][4] = {};
    int r0 = tid >> 4, lc8 = (tid & 15) * 8;
    unsigned w0 = (unsigned)(r0*272 + lc8*2);
    unsigned w1 = w0 + 16*272;
    const half* pa0 = phb + (size_t)r0*KP + m0 + lc8;
    const half* pq0 = qb  + (size_t)r0*DD + n0 + lc8;
    int arow = (lane & 7) + ((lane >> 4) << 3);
    unsigned aAO[2], aBqO[4];
    #pragma unroll
    for (int f = 0; f < 2; f++) {
        int acol = wm*32 + f*16 + ((lane >> 3) & 1) * 8;
        aAO[f] = SF_SA + (unsigned)(arow*272 + acol*2);
    }
    int brow = lane & 15, bc8 = ((lane >> 4) << 3);
    #pragma unroll
    for (int p = 0; p < 4; p++)
        aBqO[p] = SF_SQ + (unsigned)(brow*272 + (wn*64 + p*16 + bc8)*2);

    #define SF_LOAD(t, stage, sz1) do {                                       \
        unsigned so_ = (stage)*SF_SST;                                        \
        size_t ro_ = (size_t)(t)*32;                                          \
        CPA16 (sb + SF_SA + so_ + w0, pa0 + ro_*KP);                          \
        CPA16Z(sb + SF_SA + so_ + w1, pa0 + (ro_+16)*KP, sz1);                \
        CPA16 (sb + SF_SQ + so_ + w0, pq0 + ro_*DD);                          \
        CPA16Z(sb + SF_SQ + so_ + w1, pq0 + (ro_+16)*DD, sz1);                \
    } while (0)

    const int NT = (NA + 31) / 32;   /* 63; tail rows zero-filled */
    SF_LOAD(0, 0, 16); CPCOMMIT();
    SF_LOAD(1, 1, 16); CPCOMMIT();
    for (int t = 0; t < NT; t++) {
        CPWAIT1();
        __syncthreads();
        unsigned so = (t & 1) * SF_SST;
        #pragma unroll
        for (int kk2 = 0; kk2 < 2; kk2++) {
            unsigned off = sb + so + kk2*(16*272);
            unsigned af[2][4];
            ldsm4t(af[0], aAO[0]+off); ldsm4t(af[1], aAO[1]+off);
            #pragma unroll
            for (int p = 0; p < 4; p++) {
                unsigned bq[4]; ldsm4t(bq, aBqO[p]+off);
                #pragma unroll
                for (int f = 0; f < 2; f++) {
                    mma16816(acc[f][2*p  ], af[f], bq[0], bq[1]);
                    mma16816(acc[f][2*p+1], af[f], bq[2], bq[3]);
                }
            }
        }
        __syncthreads();
        if (t + 2 < NT) {
            int sz1 = (t + 2 == NT - 1) ? 0 : 16;
            SF_LOAD(t+2, t & 1, sz1);
        }
        CPCOMMIT();
    }
    float iM[9], ad;
    cell_inv(cell + b*9, iM, &ad);
    #pragma unroll
    for (int f = 0; f < 2; f++) {
        int gm0 = m0 + wm*32 + f*16 + gp, gm1 = gm0 + 8;
        float G0 = green_eval(gm0, iM, ad);
        float G1 = green_eval(gm1, iM, ad);
        #pragma unroll
        for (int nf = 0; nf < 8; nf++) {
            int gn = n0 + wn*64 + nf*8 + tg*2;
            *(half2*)&Sout[(size_t)(b*KP+gm0)*DD + gn] = __floats2half2_rn(G0*acc[f][nf][0], G0*acc[f][nf][1]);
            *(half2*)&Sout[(size_t)(b*KP+gm1)*DD + gn] = __floats2half2_rn(G1*acc[f][nf][2], G1*acc[f][nf][3]);
        }
    }
}

/* ---------------- fp16 NN fused + epilogue: out = (pot+acc+Cq)q ------------ */
/* grid (16, 2, 8), 256 threads, 8 warps 4m x 2n, occ 2, kt 32, 2-stage. */
#define KT_SSA 10240                /* A stage: 128*40*2 */
#define KT_SSB 8704                 /* B stage: 32*136*2 */
#define KT_AC 0
#define KT_AS (2*KT_SSA)
#define KT_BC (4*KT_SSA)
#define KT_BS (KT_BC + 2*KT_SSB)
#define KT_SMEM (KT_BS + 2*KT_SSB)  /* 75776 */

__global__ void __launch_bounds__(256, 2) k_pot(float* __restrict__ out) {
    extern __shared__ __align__(16) char smem[];
    unsigned sb = sptr(smem);
    int b  = blockIdx.z;
    int m0 = blockIdx.x * 128;
    int n0 = blockIdx.y * 128;
    int tid = threadIdx.x, warp = tid >> 5, lane = tid & 31;
    int wm = warp & 3, wn = warp >> 2;
    int tg = lane & 3, gp = lane >> 2;
    const half* cosb = g_cosh + (size_t)b * NA * KP;
    const half* sinb = g_sinh + (size_t)b * NA * KP;
    float acc[2][8][4] = {};
    int rowA = tid >> 1, cA8 = (tid & 1) * 8;
    int srcA = (m0 + rowA) < NA ? 16 : 0;
    int rowAc = (m0 + rowA) < NA ? (m0 + rowA) : (NA - 1);
    unsigned wA0 = (unsigned)(rowA*80 + cA8*2);
    unsigned wA1 = wA0 + 32;
    const half* pAc = cosb + (size_t)rowAc*KP + cA8;
    const half* pAs = sinb + (size_t)rowAc*KP + cA8;
    int rowB = tid >> 4, cB8 = (tid & 15) * 8;
    unsigned wB0 = (unsigned)(rowB*272 + cB8*2);
    unsigned wB1 = wB0 + 16*272;
    const half* pBc = g_Sch + (size_t)((size_t)b*KP + rowB)*DD + n0 + cB8;
    const half* pBs = g_Ssh + (size_t)((size_t)b*KP + rowB)*DD + n0 + cB8;
    int r = lane & 7, g = lane >> 3;
    unsigned aAO[2], aSO[2], aBcO[4], aBsO[4];
    #pragma unroll
    for (int f = 0; f < 2; f++) {
        int rr = wm*32 + f*16 + r + (g & 1)*8;
        int cc = (g >> 1) * 8;
        aAO[f] = KT_AC + (unsigned)(rr*80 + cc*2);
        aSO[f] = KT_AS + (unsigned)(rr*80 + cc*2);
    }
    int brow = lane & 15, bc8 = ((lane >> 4) << 3);
    #pragma unroll
    for (int p = 0; p < 4; p++) {
        aBcO[p] = KT_BC + (unsigned)(brow*272 + (wn*64 + p*16 + bc8)*2);
        aBsO[p] = KT_BS + (unsigned)(brow*272 + (wn*64 + p*16 + bc8)*2);
    }

    #define KT_LOAD(t, stage) do {                                            \
        unsigned sa_ = (stage)*KT_SSA, sbo_ = (stage)*KT_SSB;                 \
        size_t ko_ = (size_t)(t)*32;                                          \
        CPA16Z(sb + KT_AC + sa_ + wA0, pAc + ko_,      srcA);                 \
        CPA16Z(sb + KT_AC + sa_ + wA1, pAc + ko_ + 16, srcA);                 \
        CPA16Z(sb + KT_AS + sa_ + wA0, pAs + ko_,      srcA);                 \
        CPA16Z(sb + KT_AS + sa_ + wA1, pAs + ko_ + 16, srcA);                 \
        CPA16 (sb + KT_BC + sbo_ + wB0, pBc + ko_*DD);                        \
        CPA16 (sb + KT_BC + sbo_ + wB1, pBc + (ko_+16)*DD);                   \
        CPA16 (sb + KT_BS + sbo_ + wB0, pBs + ko_*DD);                        \
        CPA16 (sb + KT_BS + sbo_ + wB1, pBs + (ko_+16)*DD);                   \
    } while (0)

    const int NT = KP / 32;   /* 36 exact */
    KT_LOAD(0, 0); CPCOMMIT();
    KT_LOAD(1, 1); CPCOMMIT();
    for (int t = 0; t < NT; t++) {
        CPWAIT1();
        __syncthreads();
        unsigned sa = (t & 1) * KT_SSA, sbo = (t & 1) * KT_SSB;
        #pragma unroll
        for (int kk2 = 0; kk2 < 2; kk2++) {
            unsigned aoff = sb + sa + kk2*32;
            unsigned boff = sb + sbo + kk2*(16*272);
            unsigned af[2][4], sf_[2][4];
            ldsm4(af[0],  aAO[0]+aoff); ldsm4(af[1],  aAO[1]+aoff);
            ldsm4(sf_[0], aSO[0]+aoff); ldsm4(sf_[1], aSO[1]+aoff);
            #pragma unroll
            for (int p = 0; p < 4; p++) {
                unsigned bb[4];
                ldsm4t(bb, aBcO[p]+boff);
                #pragma unroll
                for (int f = 0; f < 2; f++) {
                    mma16816(acc[f][2*p  ], af[f], bb[0], bb[1]);
                    mma16816(acc[f][2*p+1], af[f], bb[2], bb[3]);
                }
                ldsm4t(bb, aBsO[p]+boff);
                #pragma unroll
                for (int f = 0; f < 2; f++) {
                    mma16816(acc[f][2*p  ], sf_[f], bb[0], bb[1]);
                    mma16816(acc[f][2*p+1], sf_[f], bb[2], bb[3]);
                }
            }
        }
        __syncthreads();
        if (t + 2 < NT) KT_LOAD(t+2, t & 1);
        CPCOMMIT();
    }
    #pragma unroll
    for (int f = 0; f < 2; f++) {
        int gm0 = m0 + wm*32 + f*16 + gp, gm1 = gm0 + 8;
        #pragma unroll
        for (int nf = 0; nf < 8; nf++) {
            int gn = n0 + wn*64 + nf*8 + tg*2;
            if (gm0 < NA) {
                size_t idx = (size_t)(b*NA+gm0)*DD + gn;
                float2 pr = *(const float2*)&g_pot[idx];
                float2 qv = *(const float2*)&g_q[idx];
                float2 o;
                o.x = (pr.x + acc[f][nf][0] + C_SELF*qv.x) * qv.x;
                o.y = (pr.y + acc[f][nf][1] + C_SELF*qv.y) * qv.y;
                *(float2*)&out[idx] = o;
            }
            if (gm1 < NA) {
                size_t idx = (size_t)(b*NA+gm1)*DD + gn;
                float2 pr = *(const float2*)&g_pot[idx];
                float2 qv = *(const float2*)&g_q[idx];
                float2 o;
                o.x = (pr.x + acc[f][nf][2] + C_SELF*qv.x) * qv.x;
                o.y = (pr.y + acc[f][nf][3] + C_SELF*qv.y) * qv.y;
                *(float2*)&out[idx] = o;
            }
        }
    }
}

/* ---------------- launch -------------------------------------------------- */
/* Order chosen so the 4th launch (the one ncu captures) is k_sf. */
extern "C" void kernel_launch(void* const* d_in, const int* in_sizes, int n_in,
                              void* d_out, int out_size) {
    const float* features = (const float*)d_in[0];
    const float* positions= (const float*)d_in[1];
    const float* cell     = (const float*)d_in[2];
    const int*   nbidx    = (const int*)  d_in[3];
    const float* nbdist   = (const float*)d_in[4];
    const float* W        = (const float*)d_in[5];
    const float* bias     = (const float*)d_in[6];
    float* out = (float*)d_out;

    cudaFuncSetAttribute(k_sf,  cudaFuncAttributeMaxDynamicSharedMemorySize, SF_SMEM);
    cudaFuncSetAttribute(k_pot, cudaFuncAttributeMaxDynamicSharedMemorySize, KT_SMEM);

    k_phase  <<<BB*NA, 256>>>(positions, cell);
    k_charges<<<dim3((BB*NA)/64, DD/64), 128>>>(features, W, bias);
    k_count  <<<(BB*EE+255)/256, 256>>>(nbidx);
    k_sf     <<<dim3(KP/128, 4, BB), 256, SF_SMEM>>>(cell);
    k_scan   <<<BB, 1024>>>();
    k_fill   <<<(BB*EE+255)/256, 256>>>(nbidx, nbdist);
    k_gather <<<BB*NA, 128>>>();
    k_pot    <<<dim3((NA+127)/128, DD/128, BB), 256, KT_SMEM>>>(out);
    (void)in_sizes; (void)n_in; (void)out_size;
}

// round 16
// speedup vs baseline: 1.1239x; 1.0748x over previous
#include <cuda_runtime.h>
#include <cuda_fp16.h>
#include <stdint.h>
#include <math.h>

#define BB 8
#define NA 2000
#define DD 256
#define EE 64000
#define KNUMH 1098       /* half-space k-vectors (m = 0..1097) */
#define KP 1152          /* 128 * 9, padded with G=0, cos/sin=0 */
#define PI_F 3.14159265358979f
#define C_SELF (-0.7978845608028654f)   /* -sqrt(2/pi)/sigma */

/* ---------------- scratch (device globals; no allocations allowed) -------- */
__device__ float g_q  [BB*NA*DD];
__device__ float g_pot[BB*NA*DD];
__device__ __align__(16) half g_qh  [BB*NA*DD];
__device__ __align__(16) half g_cosh[(size_t)BB*NA*KP];
__device__ __align__(16) half g_sinh[(size_t)BB*NA*KP];
__device__ __align__(16) half g_Sch [BB*KP*DD];
__device__ __align__(16) half g_Ssh [BB*KP*DD];
__device__ int   g_cnt[BB*NA];
__device__ int   g_off[BB*NA];
__device__ int   g_fil[BB*NA];
__device__ int   g_elj[BB*EE];
__device__ float g_elv[BB*EE];

/* ---------------- MMA / ldmatrix / cp.async helpers ------------------------ */
__device__ __forceinline__ unsigned sptr(const void* p) {
    return (unsigned)__cvta_generic_to_shared(p);
}
__device__ __forceinline__ void ldsm4(unsigned* r, unsigned a) {
    asm volatile("ldmatrix.sync.aligned.m8n8.x4.shared.b16 {%0,%1,%2,%3},[%4];"
        : "=r"(r[0]), "=r"(r[1]), "=r"(r[2]), "=r"(r[3]) : "r"(a));
}
__device__ __forceinline__ void ldsm4t(unsigned* r, unsigned a) {
    asm volatile("ldmatrix.sync.aligned.m8n8.x4.trans.shared.b16 {%0,%1,%2,%3},[%4];"
        : "=r"(r[0]), "=r"(r[1]), "=r"(r[2]), "=r"(r[3]) : "r"(a));
}
__device__ __forceinline__ void mma16816(float* d, const unsigned* a,
                                         unsigned b0, unsigned b1) {
    asm volatile(
        "mma.sync.aligned.m16n8k16.row.col.f32.f16.f16.f32 "
        "{%0,%1,%2,%3},{%4,%5,%6,%7},{%8,%9},{%0,%1,%2,%3};"
        : "+f"(d[0]), "+f"(d[1]), "+f"(d[2]), "+f"(d[3])
        : "r"(a[0]), "r"(a[1]), "r"(a[2]), "r"(a[3]), "r"(b0), "r"(b1));
}
__device__ __forceinline__ unsigned f2tf(float x) {
    unsigned r; asm("cvt.rna.tf32.f32 %0, %1;" : "=r"(r) : "f"(x)); return r;
}
__device__ __forceinline__ void mma_tf32(float* d, unsigned a0, unsigned a1,
                                         unsigned a2, unsigned a3,
                                         unsigned b0, unsigned b1) {
    asm volatile(
        "mma.sync.aligned.m16n8k8.row.col.f32.tf32.tf32.f32 "
        "{%0,%1,%2,%3},{%4,%5,%6,%7},{%8,%9},{%0,%1,%2,%3};"
        : "+f"(d[0]), "+f"(d[1]), "+f"(d[2]), "+f"(d[3])
        : "r"(a0), "r"(a1), "r"(a2), "r"(a3), "r"(b0), "r"(b1));
}
#define CPA16(d, s)     asm volatile("cp.async.ca.shared.global [%0], [%1], 16;" :: "r"(d), "l"(s))
#define CPA16Z(d, s, n) asm volatile("cp.async.ca.shared.global [%0], [%1], 16, %2;" :: "r"(d), "l"(s), "r"(n))
#define CPCOMMIT()      asm volatile("cp.async.commit_group;")
#define CPWAIT1()       asm volatile("cp.async.wait_group 1;")

/* ---------------- Green's function evaluation (inline) --------------------- */
__device__ __forceinline__ void cell_inv(const float* C, float* iM, float* absdet) {
    float c00=C[0],c01=C[1],c02=C[2];
    float c10=C[3],c11=C[4],c12=C[5];
    float c20=C[6],c21=C[7],c22=C[8];
    float det = c00*(c11*c22-c12*c21) - c01*(c10*c22-c12*c20) + c02*(c10*c21-c11*c20);
    float id = 1.0f/det;
    iM[0]=(c11*c22-c12*c21)*id; iM[1]=(c02*c21-c01*c22)*id; iM[2]=(c01*c12-c02*c11)*id;
    iM[3]=(c12*c20-c10*c22)*id; iM[4]=(c00*c22-c02*c20)*id; iM[5]=(c02*c10-c00*c12)*id;
    iM[6]=(c10*c21-c11*c20)*id; iM[7]=(c01*c20-c00*c21)*id; iM[8]=(c00*c11-c01*c10)*id;
    *absdet = fabsf(det);
}
__device__ __forceinline__ float green_eval(int k, const float* iM, float absdet) {
    if (k >= KNUMH) return 0.f;
    float ni = (float)(k/169 - 6);
    float nj = (float)((k/13)%13 - 6);
    float nk = (float)(k%13 - 6);
    float kx = 2.0f*PI_F*(iM[0]*ni + iM[1]*nj + iM[2]*nk);
    float ky = 2.0f*PI_F*(iM[3]*ni + iM[4]*nj + iM[5]*nk);
    float kz = 2.0f*PI_F*(iM[6]*ni + iM[7]*nj + iM[8]*nk);
    float k2 = kx*kx + ky*ky + kz*kz;
    return 8.0f*PI_F/absdet * __expf(-0.5f*k2) / k2;   /* x2 for ±k pair */
}

/* ---------------- charges = features @ W^T + b (tf32 MMA) ------------------ */
/* grid (250, 4), 128 threads. tiles 64m x 64n, kt 16. */
__global__ void k_charges(const float* __restrict__ A, const float* __restrict__ Wm,
                          const float* __restrict__ bias) {
    __shared__ unsigned sA[64][20];
    __shared__ unsigned sB[16][72];
    int m0 = blockIdx.x * 64, n0 = blockIdx.y * 64;
    int tid = threadIdx.x, warp = tid >> 5, lane = tid & 31;
    int tg = lane & 3, gp = lane >> 2;
    int mb = warp * 16;
    float acc[8][4] = {};
    for (int kt = 0; kt < 256; kt += 16) {
        #pragma unroll
        for (int i = 0; i < 2; i++) {
            int t = tid + i*128;
            int row = t >> 2, k4 = (t & 3) * 4;
            float4 v = *(const float4*)&A[(size_t)(m0+row)*256 + kt + k4];
            sA[row][k4+0]=f2tf(v.x); sA[row][k4+1]=f2tf(v.y);
            sA[row][k4+2]=f2tf(v.z); sA[row][k4+3]=f2tf(v.w);
            float4 w = *(const float4*)&Wm[(size_t)(n0+row)*256 + kt + k4];
            sB[k4+0][row]=f2tf(w.x); sB[k4+1][row]=f2tf(w.y);
            sB[k4+2][row]=f2tf(w.z); sB[k4+3][row]=f2tf(w.w);
        }
        __syncthreads();
        #pragma unroll
        for (int k0 = 0; k0 < 16; k0 += 8) {
            unsigned a0 = sA[mb+gp  ][k0+tg],   a1 = sA[mb+8+gp][k0+tg];
            unsigned a2 = sA[mb+gp  ][k0+tg+4], a3 = sA[mb+8+gp][k0+tg+4];
            #pragma unroll
            for (int n8 = 0; n8 < 8; n8++) {
                unsigned b0 = sB[k0+tg  ][n8*8+gp];
                unsigned b1 = sB[k0+tg+4][n8*8+gp];
                mma_tf32(acc[n8], a0, a1, a2, a3, b0, b1);
            }
        }
        __syncthreads();
    }
    int gm0 = m0 + mb + gp, gm1 = gm0 + 8;
    #pragma unroll
    for (int n8 = 0; n8 < 8; n8++) {
        int gn = n0 + n8*8 + tg*2;
        float b0 = bias[gn], b1 = bias[gn+1];
        float v0 = acc[n8][0] + b0, v1 = acc[n8][1] + b1;
        float v2 = acc[n8][2] + b0, v3 = acc[n8][3] + b1;
        *(float2*)&g_q[(size_t)gm0*DD + gn] = make_float2(v0, v1);
        *(float2*)&g_q[(size_t)gm1*DD + gn] = make_float2(v2, v3);
        *(half2*)&g_qh[(size_t)gm0*DD + gn] = __floats2half2_rn(v0, v1);
        *(half2*)&g_qh[(size_t)gm1*DD + gn] = __floats2half2_rn(v2, v3);
    }
}

/* ------ phases via separable axis factors; also zeroes edge counters ------- */
__global__ void k_phase(const float* __restrict__ pos, const float* __restrict__ cell) {
    __shared__ float er[3][13], ei[3][13];
    int bn = blockIdx.x;
    int b  = bn / NA;
    int tid = threadIdx.x;
    if (tid == 64) g_cnt[bn] = 0;
    if (tid == 96) g_fil[bn] = 0;
    float px = pos[bn*3+0], py = pos[bn*3+1], pz = pos[bn*3+2];
    if (tid < 39) {
        float iM[9], ad;
        cell_inv(cell + b*9, iM, &ad);
        int axis = tid / 13, idx = tid % 13;
        float u;
        if      (axis == 0) u = iM[0]*px + iM[3]*py + iM[6]*pz;
        else if (axis == 1) u = iM[1]*px + iM[4]*py + iM[7]*pz;
        else                u = iM[2]*px + iM[5]*py + iM[8]*pz;
        float ph = 2.0f*PI_F * u * (float)(idx - 6);
        float s, c; __sincosf(ph, &s, &c);
        er[axis][idx] = c; ei[axis][idx] = s;
    }
    __syncthreads();
    size_t base = (size_t)bn * KP;
    for (int k2 = tid; k2 < KP/2; k2 += 256) {
        int k = k2 * 2;
        float c0=0.f, s0=0.f, c1=0.f, s1=0.f;
        #pragma unroll
        for (int h = 0; h < 2; h++) {
            int m = k + h;
            if (m < KNUMH) {
                int i = m / 169; int r = m - i*169;
                int j = r / 13;  int l = r - j*13;
                float ar = er[0][i], ai = ei[0][i];
                float br = er[1][j], bi = ei[1][j];
                float tr = ar*br - ai*bi, ti = ar*bi + ai*br;
                float cr = er[2][l], ci = ei[2][l];
                float cc = tr*cr - ti*ci, ss = tr*ci + ti*cr;
                if (h == 0) { c0 = cc; s0 = ss; } else { c1 = cc; s1 = ss; }
            }
        }
        *(half2*)&g_cosh[base + k] = __floats2half2_rn(c0, c1);
        *(half2*)&g_sinh[base + k] = __floats2half2_rn(s0, s1);
    }
}

/* ---------------- edge pipeline: count -> scan -> fill -> gather ----------- */
__global__ void k_count(const int* __restrict__ nbidx) {
    int e = blockIdx.x * blockDim.x + threadIdx.x;
    if (e >= BB*EE) return;
    int b = e / EE;
    int i = nbidx[e*2];
    atomicAdd(&g_cnt[b*NA + i], 1);
}

__global__ void k_scan() {
    __shared__ int s[2048];
    int b = blockIdx.x, tid = threadIdx.x;
    #pragma unroll
    for (int i = 0; i < 2; i++) {
        int idx = tid + i*1024;
        s[idx] = (idx < NA) ? g_cnt[b*NA + idx] : 0;
    }
    int offset = 1;
    for (int d = 1024; d > 0; d >>= 1) {
        __syncthreads();
        if (tid < d) {
            int ai = offset*(2*tid+1) - 1;
            int bi = offset*(2*tid+2) - 1;
            s[bi] += s[ai];
        }
        offset <<= 1;
    }
    if (tid == 0) s[2047] = 0;
    for (int d = 1; d < 2048; d <<= 1) {
        offset >>= 1;
        __syncthreads();
        if (tid < d) {
            int ai = offset*(2*tid+1) - 1;
            int bi = offset*(2*tid+2) - 1;
            int t = s[ai]; s[ai] = s[bi]; s[bi] += t;
        }
    }
    __syncthreads();
    #pragma unroll
    for (int i = 0; i < 2; i++) {
        int idx = tid + i*1024;
        if (idx < NA) g_off[b*NA + idx] = s[idx];
    }
}

__global__ void k_fill(const int* __restrict__ nbidx, const float* __restrict__ nbdist) {
    int e = blockIdx.x * blockDim.x + threadIdx.x;
    if (e >= BB*EE) return;
    int b = e / EE;
    int i = nbidx[e*2 + 0];
    int j = nbidx[e*2 + 1];
    float d = nbdist[e];
    float v  = erfcf(d * 0.70710678118f) / d;
    float fc = (d < 5.0f) ? 0.5f*(__cosf(PI_F * d * 0.2f) + 1.0f) : 0.0f;
    float vsr = v - fc / d;
    int pos = g_off[b*NA + i] + atomicAdd(&g_fil[b*NA + i], 1);
    g_elj[b*EE + pos] = j;
    g_elv[b*EE + pos] = vsr;
}

/* 128 threads: 4 warps x 4 concurrent edges, uint4 (8-chan) loads,
   cross-warp smem reduction. */
__global__ void k_gather() {
    __shared__ float red[4][256];
    int bn = blockIdx.x;
    int b  = bn / NA;
    int tid = threadIdx.x, warp = tid >> 5, lane = tid & 31;
    int start = g_off[bn];
    int cnt   = g_cnt[bn];
    const int*   ej = g_elj + b*EE + start;
    const float* ev = g_elv + b*EE + start;
    const uint4* qb = (const uint4*)(g_qh + (size_t)b*NA*DD);   /* 32 uint4/row */
    float acc[8] = {};
    for (int e = warp; e < cnt; e += 4) {
        int   j = ej[e];
        float v = ev[e];
        uint4 u = qb[(size_t)j*32 + lane];
        half2* h = (half2*)&u;
        #pragma unroll
        for (int p = 0; p < 4; p++) {
            float2 f = __half22float2(h[p]);
            acc[2*p]   += v * f.x;
            acc[2*p+1] += v * f.y;
        }
    }
    #pragma unroll
    for (int p = 0; p < 8; p++) red[warp][lane*8 + p] = acc[p];
    __syncthreads();
    int c = tid * 2;
    float s0 = red[0][c]   + red[1][c]   + red[2][c]   + red[3][c];
    float s1 = red[0][c+1] + red[1][c+1] + red[2][c+1] + red[3][c+1];
    *(float2*)&g_pot[(size_t)bn*DD + c] = make_float2(s0, s1);
}

/* ---------------- fp16 TN: S{c|s} = G*(ph^T q), cos/sin split -------------- */
/* grid (9, 4, 8): y = (cs<<1)|n-tile. 256 threads, 8 warps 4m x 2n.         */
/* tile 128m x 128n, kt 32, 2-stage cp.async, occ 2.                          */
#define SF_SST 8704                 /* one stage of one array: 32*136*2 bytes */
#define SF_SA 0
#define SF_SQ (2*SF_SST)
#define SF_SMEM (4*SF_SST)          /* 34816 */

__global__ void __launch_bounds__(256, 2) k_sf(const float* __restrict__ cell) {
    extern __shared__ __align__(16) char smem[];
    unsigned sb = sptr(smem);
    int b  = blockIdx.z;
    int m0 = blockIdx.x * 128;
    int yb = blockIdx.y;
    int n0 = (yb & 1) * 128;
    int cs = yb >> 1;                       /* 0 = cos->Sc, 1 = sin->Ss */
    int tid = threadIdx.x, warp = tid >> 5, lane = tid & 31;
    int wm = warp & 3, wn = warp >> 2;
    int tg = lane & 3, gp = lane >> 2;
    const half* phb = (cs ? g_sinh : g_cosh) + (size_t)b * NA * KP;
    const half* qb  = g_qh + (size_t)b * NA * DD;
    half* Sout = (cs ? g_Ssh : g_Sch);
    float acc[2][8][4] = {};
    int r0 = tid >> 4, lc8 = (tid & 15) * 8;
    unsigned w0 = (unsigned)(r0*272 + lc8*2);
    unsigned w1 = w0 + 16*272;
    const half* pa0 = phb + (size_t)r0*KP + m0 + lc8;
    const half* pq0 = qb  + (size_t)r0*DD + n0 + lc8;
    int arow = (lane & 7) + ((lane >> 4) << 3);
    unsigned aAO[2], aBqO[4];
    #pragma unroll
    for (int f = 0; f < 2; f++) {
        int acol = wm*32 + f*16 + ((lane >> 3) & 1) * 8;
        aAO[f] = SF_SA + (unsigned)(arow*272 + acol*2);
    }
    int brow = lane & 15, bc8 = ((lane >> 4) << 3);
    #pragma unroll
    for (int p = 0; p < 4; p++)
        aBqO[p] = SF_SQ + (unsigned)(brow*272 + (wn*64 + p*16 + bc8)*2);

    #define SF_LOAD(t, stage, sz1) do {                                       \
        unsigned so_ = (stage)*SF_SST;                                        \
        size_t ro_ = (size_t)(t)*32;                                          \
        CPA16 (sb + SF_SA + so_ + w0, pa0 + ro_*KP);                          \
        CPA16Z(sb + SF_SA + so_ + w1, pa0 + (ro_+16)*KP, sz1);                \
        CPA16 (sb + SF_SQ + so_ + w0, pq0 + ro_*DD);                          \
        CPA16Z(sb + SF_SQ + so_ + w1, pq0 + (ro_+16)*DD, sz1);                \
    } while (0)

    const int NT = (NA + 31) / 32;   /* 63; tail rows zero-filled */
    SF_LOAD(0, 0, 16); CPCOMMIT();
    SF_LOAD(1, 1, 16); CPCOMMIT();
    for (int t = 0; t < NT; t++) {
        CPWAIT1();
        __syncthreads();
        unsigned so = (t & 1) * SF_SST;
        #pragma unroll
        for (int kk2 = 0; kk2 < 2; kk2++) {
            unsigned off = sb + so + kk2*(16*272);
            unsigned af[2][4];
            ldsm4t(af[0], aAO[0]+off); ldsm4t(af[1], aAO[1]+off);
            #pragma unroll
            for (int p = 0; p < 4; p++) {
                unsigned bq[4]; ldsm4t(bq, aBqO[p]+off);
                #pragma unroll
                for (int f = 0; f < 2; f++) {
                    mma16816(acc[f][2*p  ], af[f], bq[0], bq[1]);
                    mma16816(acc[f][2*p+1], af[f], bq[2], bq[3]);
                }
            }
        }
        __syncthreads();
        if (t + 2 < NT) {
            int sz1 = (t + 2 == NT - 1) ? 0 : 16;
            SF_LOAD(t+2, t & 1, sz1);
        }
        CPCOMMIT();
    }
    float iM[9], ad;
    cell_inv(cell + b*9, iM, &ad);
    #pragma unroll
    for (int f = 0; f < 2; f++) {
        int gm0 = m0 + wm*32 + f*16 + gp, gm1 = gm0 + 8;
        float G0 = green_eval(gm0, iM, ad);
        float G1 = green_eval(gm1, iM, ad);
        #pragma unroll
        for (int nf = 0; nf < 8; nf++) {
            int gn = n0 + wn*64 + nf*8 + tg*2;
            *(half2*)&Sout[(size_t)(b*KP+gm0)*DD + gn] = __floats2half2_rn(G0*acc[f][nf][0], G0*acc[f][nf][1]);
            *(half2*)&Sout[(size_t)(b*KP+gm1)*DD + gn] = __floats2half2_rn(G1*acc[f][nf][2], G1*acc[f][nf][3]);
        }
    }
}

/* ---------------- fp16 NN fused + epilogue: out = (pot+acc+Cq)q ------------ */
/* grid (16, 2, 8), 256 threads, 8 warps 4m x 2n, occ 2, kt 32, 2-stage. */
#define KT_SSA 10240                /* A stage: 128*40*2 */
#define KT_SSB 8704                 /* B stage: 32*136*2 */
#define KT_AC 0
#define KT_AS (2*KT_SSA)
#define KT_BC (4*KT_SSA)
#define KT_BS (KT_BC + 2*KT_SSB)
#define KT_SMEM (KT_BS + 2*KT_SSB)  /* 75776 */

__global__ void __launch_bounds__(256, 2) k_pot(float* __restrict__ out) {
    extern __shared__ __align__(16) char smem[];
    unsigned sb = sptr(smem);
    int b  = blockIdx.z;
    int m0 = blockIdx.x * 128;
    int n0 = blockIdx.y * 128;
    int tid = threadIdx.x, warp = tid >> 5, lane = tid & 31;
    int wm = warp & 3, wn = warp >> 2;
    int tg = lane & 3, gp = lane >> 2;
    const half* cosb = g_cosh + (size_t)b * NA * KP;
    const half* sinb = g_sinh + (size_t)b * NA * KP;
    float acc[2][8][4] = {};
    int rowA = tid >> 1, cA8 = (tid & 1) * 8;
    int srcA = (m0 + rowA) < NA ? 16 : 0;
    int rowAc = (m0 + rowA) < NA ? (m0 + rowA) : (NA - 1);
    unsigned wA0 = (unsigned)(rowA*80 + cA8*2);
    unsigned wA1 = wA0 + 32;
    const half* pAc = cosb + (size_t)rowAc*KP + cA8;
    const half* pAs = sinb + (size_t)rowAc*KP + cA8;
    int rowB = tid >> 4, cB8 = (tid & 15) * 8;
    unsigned wB0 = (unsigned)(rowB*272 + cB8*2);
    unsigned wB1 = wB0 + 16*272;
    const half* pBc = g_Sch + (size_t)((size_t)b*KP + rowB)*DD + n0 + cB8;
    const half* pBs = g_Ssh + (size_t)((size_t)b*KP + rowB)*DD + n0 + cB8;
    int r = lane & 7, g = lane >> 3;
    unsigned aAO[2], aSO[2], aBcO[4], aBsO[4];
    #pragma unroll
    for (int f = 0; f < 2; f++) {
        int rr = wm*32 + f*16 + r + (g & 1)*8;
        int cc = (g >> 1) * 8;
        aAO[f] = KT_AC + (unsigned)(rr*80 + cc*2);
        aSO[f] = KT_AS + (unsigned)(rr*80 + cc*2);
    }
    int brow = lane & 15, bc8 = ((lane >> 4) << 3);
    #pragma unroll
    for (int p = 0; p < 4; p++) {
        aBcO[p] = KT_BC + (unsigned)(brow*272 + (wn*64 + p*16 + bc8)*2);
        aBsO[p] = KT_BS + (unsigned)(brow*272 + (wn*64 + p*16 + bc8)*2);
    }

    #define KT_LOAD(t, stage) do {                                            \
        unsigned sa_ = (stage)*KT_SSA, sbo_ = (stage)*KT_SSB;                 \
        size_t ko_ = (size_t)(t)*32;                                          \
        CPA16Z(sb + KT_AC + sa_ + wA0, pAc + ko_,      srcA);                 \
        CPA16Z(sb + KT_AC + sa_ + wA1, pAc + ko_ + 16, srcA);                 \
        CPA16Z(sb + KT_AS + sa_ + wA0, pAs + ko_,      srcA);                 \
        CPA16Z(sb + KT_AS + sa_ + wA1, pAs + ko_ + 16, srcA);                 \
        CPA16 (sb + KT_BC + sbo_ + wB0, pBc + ko_*DD);                        \
        CPA16 (sb + KT_BC + sbo_ + wB1, pBc + (ko_+16)*DD);                   \
        CPA16 (sb + KT_BS + sbo_ + wB0, pBs + ko_*DD);                        \
        CPA16 (sb + KT_BS + sbo_ + wB1, pBs + (ko_+16)*DD);                   \
    } while (0)

    const int NT = KP / 32;   /* 36 exact */
    KT_LOAD(0, 0); CPCOMMIT();
    KT_LOAD(1, 1); CPCOMMIT();
    for (int t = 0; t < NT; t++) {
        CPWAIT1();
        __syncthreads();
        unsigned sa = (t & 1) * KT_SSA, sbo = (t & 1) * KT_SSB;
        #pragma unroll
        for (int kk2 = 0; kk2 < 2; kk2++) {
            unsigned aoff = sb + sa + kk2*32;
            unsigned boff = sb + sbo + kk2*(16*272);
            unsigned af[2][4], sf_[2][4];
            ldsm4(af[0],  aAO[0]+aoff); ldsm4(af[1],  aAO[1]+aoff);
            ldsm4(sf_[0], aSO[0]+aoff); ldsm4(sf_[1], aSO[1]+aoff);
            #pragma unroll
            for (int p = 0; p < 4; p++) {
                unsigned bb[4];
                ldsm4t(bb, aBcO[p]+boff);
                #pragma unroll
                for (int f = 0; f < 2; f++) {
                    mma16816(acc[f][2*p  ], af[f], bb[0], bb[1]);
                    mma16816(acc[f][2*p+1], af[f], bb[2], bb[3]);
                }
                ldsm4t(bb, aBsO[p]+boff);
                #pragma unroll
                for (int f = 0; f < 2; f++) {
                    mma16816(acc[f][2*p  ], sf_[f], bb[0], bb[1]);
                    mma16816(acc[f][2*p+1], sf_[f], bb[2], bb[3]);
                }
            }
        }
        __syncthreads();
        if (t + 2 < NT) KT_LOAD(t+2, t & 1);
        CPCOMMIT();
    }
    #pragma unroll
    for (int f = 0; f < 2; f++) {
        int gm0 = m0 + wm*32 + f*16 + gp, gm1 = gm0 + 8;
        #pragma unroll
        for (int nf = 0; nf < 8; nf++) {
            int gn = n0 + wn*64 + nf*8 + tg*2;
            if (gm0 < NA) {
                size_t idx = (size_t)(b*NA+gm0)*DD + gn;
                float2 pr = *(const float2*)&g_pot[idx];
                float2 qv = *(const float2*)&g_q[idx];
                float2 o;
                o.x = (pr.x + acc[f][nf][0] + C_SELF*qv.x) * qv.x;
                o.y = (pr.y + acc[f][nf][1] + C_SELF*qv.y) * qv.y;
                *(float2*)&out[idx] = o;
            }
            if (gm1 < NA) {
                size_t idx = (size_t)(b*NA+gm1)*DD + gn;
                float2 pr = *(const float2*)&g_pot[idx];
                float2 qv = *(const float2*)&g_q[idx];
                float2 o;
                o.x = (pr.x + acc[f][nf][2] + C_SELF*qv.x) * qv.x;
                o.y = (pr.y + acc[f][nf][3] + C_SELF*qv.y) * qv.y;
                *(float2*)&out[idx] = o;
            }
        }
    }
}

/* ---------------- launch: fork/join stream overlap ------------------------- */
/* chain A (stream 0): phase -> charges -> sf -> pot                          */
/* chain B (stream s1): [phase] count -> scan -> fill -> [charges] gather     */
/* pot waits on the join event from chain B.                                  */
extern "C" void kernel_launch(void* const* d_in, const int* in_sizes, int n_in,
                              void* d_out, int out_size) {
    const float* features = (const float*)d_in[0];
    const float* positions= (const float*)d_in[1];
    const float* cell     = (const float*)d_in[2];
    const int*   nbidx    = (const int*)  d_in[3];
    const float* nbdist   = (const float*)d_in[4];
    const float* W        = (const float*)d_in[5];
    const float* bias     = (const float*)d_in[6];
    float* out = (float*)d_out;

    static cudaStream_t s1 = 0;
    static cudaEvent_t evPhase = 0, evCharges = 0, evJoin = 0;
    if (s1 == 0) {
        cudaStreamCreateWithFlags(&s1, cudaStreamNonBlocking);
        cudaEventCreateWithFlags(&evPhase,   cudaEventDisableTiming);
        cudaEventCreateWithFlags(&evCharges, cudaEventDisableTiming);
        cudaEventCreateWithFlags(&evJoin,    cudaEventDisableTiming);
        cudaFuncSetAttribute(k_sf,  cudaFuncAttributeMaxDynamicSharedMemorySize, SF_SMEM);
        cudaFuncSetAttribute(k_pot, cudaFuncAttributeMaxDynamicSharedMemorySize, KT_SMEM);
    }

    /* chain A prefix */
    k_phase  <<<BB*NA, 256, 0, 0>>>(positions, cell);
    cudaEventRecord(evPhase, 0);
    k_charges<<<dim3((BB*NA)/64, DD/64), 128, 0, 0>>>(features, W, bias);
    cudaEventRecord(evCharges, 0);

    /* chain B forked off phase (and later charges) */
    cudaStreamWaitEvent(s1, evPhase, 0);
    k_count  <<<(BB*EE+255)/256, 256, 0, s1>>>(nbidx);

    /* chain A continues (4th kernel issued = k_sf for ncu) */
    k_sf     <<<dim3(KP/128, 4, BB), 256, SF_SMEM, 0>>>(cell);

    k_scan   <<<BB, 1024, 0, s1>>>();
    k_fill   <<<(BB*EE+255)/256, 256, 0, s1>>>(nbidx, nbdist);
    cudaStreamWaitEvent(s1, evCharges, 0);
    k_gather <<<BB*NA, 128, 0, s1>>>();
    cudaEventRecord(evJoin, s1);

    /* join, then final GEMM + epilogue */
    cudaStreamWaitEvent(0, evJoin, 0);
    k_pot    <<<dim3((NA+127)/128, DD/128, BB), 256, KT_SMEM, 0>>>(out);
    (void)in_sizes; (void)n_in; (void)out_size;
}